// round 14
// baseline (speedup 1.0000x reference)
#include <cuda_runtime.h>
#include <cstdint>

// LinearAttention: B=16, DK=64, N=8192, DV=64, fp32.
//   ktv[b,k,j] = sum_n k[b,n,k] * v[b,n,j]
//   out[b,n,j] = sum_k q[b,k,n] * ktv[b,k,j]
// Inputs: q [B,DK,N], k [B,N,DK], v [B,N,DV]. Output [B,N,DV] fp32.
//
// mma.sync.m16n8k16.bf16 3-term truncation split (x = hi + lo), as R12, but
// re-warped to 256 threads / 8 warps per block (j-dim split across warps) to
// lift occupancy 16 -> 24 warps/SM: R12 profile showed pure latency exposure
// (DRAM 43%, tensor 26%, issue 29%, occ 21.5% -- nothing saturated).

#define BATCH  16
#define DKC    64
#define NSEQ   8192
#define DVC    64
#define S1B    64                 // phase-1 blocks per batch
#define ROWS_PB (NSEQ / S1B)      // 128
#define TROWS  32
#define NTILES (ROWS_PB / TROWS)  // 4
#define KS     68                 // phase1 k fp32 smem stride (words)
#define VSP    136                // packed v words per n-rowpair
#define QS2    132                // phase2 q fp32 stride
#define KTP    136                // packed ktv words per dk-rowpair

#define P2_SMEM (DKC * QS2 * 4 + 32 * KTP * 4)   // 51200 B

__device__ float g_part[BATCH * S1B * DKC * DVC];  // 16 MB partial ktv
__device__ float g_ktv [BATCH * DKC * DVC];

// ---------------- helpers ----------------
__device__ __forceinline__ void cp16(uint32_t dst, const void* src) {
    asm volatile("cp.async.cg.shared.global [%0], [%1], 16;" :: "r"(dst), "l"(src));
}
__device__ __forceinline__ void cp_commit() { asm volatile("cp.async.commit_group;"); }
__device__ __forceinline__ void cp_wait0()  { asm volatile("cp.async.wait_group 0;"); }
__device__ __forceinline__ uint32_t smem_u32(const void* p) {
    uint32_t a;
    asm("{ .reg .u64 t; cvta.to.shared.u64 t, %1; cvt.u32.u64 %0, t; }" : "=r"(a) : "l"(p));
    return a;
}
__device__ __forceinline__ float trunc_hi(float x) {
    return __uint_as_float(__float_as_uint(x) & 0xFFFF0000u);
}
__device__ __forceinline__ uint32_t prmt_hi(float x0, float x1) {
    uint32_t r;
    asm("prmt.b32 %0, %1, %2, 0x7632;" : "=r"(r)
        : "r"(__float_as_uint(x0)), "r"(__float_as_uint(x1)));
    return r;
}
__device__ __forceinline__ uint32_t cvt_lo(float l0, float l1) {
    uint32_t r;
    asm("cvt.rn.bf16x2.f32 %0, %1, %2;" : "=r"(r) : "f"(l1), "f"(l0));
    return r;
}
__device__ __forceinline__ void split_pair(float x0, float x1,
                                           uint32_t& hi, uint32_t& lo) {
    hi = prmt_hi(x0, x1);
    lo = cvt_lo(x0 - trunc_hi(x0), x1 - trunc_hi(x1));
}
__device__ __forceinline__ void mma_bf16(float* d, const uint32_t* a,
                                         uint32_t b0, uint32_t b1) {
    asm volatile("mma.sync.aligned.m16n8k16.row.col.f32.bf16.bf16.f32 "
                 "{%0,%1,%2,%3}, {%4,%5,%6,%7}, {%8,%9}, {%0,%1,%2,%3};"
                 : "+f"(d[0]), "+f"(d[1]), "+f"(d[2]), "+f"(d[3])
                 : "r"(a[0]), "r"(a[1]), "r"(a[2]), "r"(a[3]), "r"(b0), "r"(b1));
}

// ============================================================================
// Phase 1: partial ktv = k_chunk^T @ v_chunk.
// Block 256 thr = 8 warps: warp = (dkg 0..3, jg 0..1); warp tile 16dk x 32j.
// mma m16n8k16: m=dk, k=n, n'=j.
//   A = k_tile[n][dk] fp32 (split+paired in-loop);
//   B = v pre-split packed [n-rowpair][g][jt][hi,lo].
// ============================================================================
__global__ __launch_bounds__(256, 3) void phase1_kernel(
    const float* __restrict__ kmat, const float* __restrict__ vmat)
{
    __shared__ float    ks[2][TROWS * KS];     // 17408 B
    __shared__ uint32_t vs[2][16 * VSP];       // 17408 B

    const int b    = blockIdx.y;
    const int blk  = blockIdx.x;
    const int t    = threadIdx.x;
    const int w    = t >> 5;
    const int dkg  = w >> 1;
    const int jg   = w & 1;
    const int lane = t & 31;
    const int g    = lane >> 2;
    const int tg   = lane & 3;
    const int kd0  = 16 * dkg;

    float acc[4][4];
#pragma unroll
    for (int jl = 0; jl < 4; jl++)
#pragma unroll
        for (int p = 0; p < 4; p++) acc[jl][p] = 0.f;

    const long base = ((long)b * NSEQ + (long)blk * ROWS_PB) * 64;
    const float4* kg4 = (const float4*)(kmat + base);
    const float4* vg4 = (const float4*)(vmat + base);
    const uint32_t ks_addr = smem_u32(&ks[0][0]);

    auto cp_k = [&](int buf, int T) {
        const float4* kp = kg4 + T * 512;
        uint32_t kb = ks_addr + (uint32_t)buf * TROWS * KS * 4;
#pragma unroll
        for (int i = 0; i < 2; i++) {
            int idx = t + i * 256;
            int r = idx >> 4, c4 = idx & 15;
            cp16(kb + (uint32_t)(r * KS + c4 * 4) * 4, kp + idx);
        }
        cp_commit();
    };

    // v producer: 1 task/thread (rp = n-rowpair 0..15, c4 = float4 col 0..15)
    float4 vA, vB;
    auto ldg_v = [&](int T) {
        int rp = t >> 4, c4 = t & 15;
        vA = vg4[T * 512 + (2 * rp) * 16 + c4];
        vB = vg4[T * 512 + (2 * rp + 1) * 16 + c4];
    };
    auto sts_v = [&](int buf) {
        uint32_t* vb = vs[buf];
        int rp = t >> 4, c4 = t & 15;
        const float* f0 = (const float*)&vA;
        const float* f1 = (const float*)&vB;
#pragma unroll
        for (int e = 0; e < 4; e++) {
            int j = c4 * 4 + e;
            uint32_t hi, lo;
            split_pair(f0[e], f1[e], hi, lo);   // low half = even n row
            *(uint2*)(vb + rp * VSP + (j & 7) * 16 + (j >> 3) * 2) =
                make_uint2(hi, lo);
        }
    };

    cp_k(0, 0);
    ldg_v(0);

    for (int T = 0; T < NTILES; T++) {
        const int buf = T & 1;
        cp_wait0();
        sts_v(buf);
        __syncthreads();
        if (T + 1 < NTILES) {
            cp_k(buf ^ 1, T + 1);
            ldg_v(T + 1);
        }

        const float*    kb = ks[buf];
        const uint32_t* vb = vs[buf];

#pragma unroll
        for (int nc = 0; nc < 2; nc++) {          // two 16-row chunks
            const int n0 = nc * 16 + 2 * tg;      // even n of b0 pair
            const int n2 = n0 + 8;
            const int c0 = kd0 + g, c1 = c0 + 8;

            uint32_t ah[4], al[4];
            split_pair(kb[n0 * KS + c0], kb[(n0 + 1) * KS + c0], ah[0], al[0]);
            split_pair(kb[n0 * KS + c1], kb[(n0 + 1) * KS + c1], ah[1], al[1]);
            split_pair(kb[n2 * KS + c0], kb[(n2 + 1) * KS + c0], ah[2], al[2]);
            split_pair(kb[n2 * KS + c1], kb[(n2 + 1) * KS + c1], ah[3], al[3]);

            const uint32_t* p0 = vb + (nc * 8 + tg) * VSP + g * 16 + jg * 8;
            const uint32_t* p1 = p0 + 4 * VSP;
#pragma unroll
            for (int qv = 0; qv < 2; qv++) {
                uint4 X0 = *(const uint4*)(p0 + qv * 4);
                uint4 X1 = *(const uint4*)(p1 + qv * 4);
                const int j0 = 2 * qv, j1 = j0 + 1;
                mma_bf16(acc[j0], ah, X0.x, X1.x);   // hi*hi
                mma_bf16(acc[j0], ah, X0.y, X1.y);   // hi*lo
                mma_bf16(acc[j0], al, X0.x, X1.x);   // lo*hi
                mma_bf16(acc[j1], ah, X0.z, X1.z);
                mma_bf16(acc[j1], ah, X0.w, X1.w);
                mma_bf16(acc[j1], al, X0.z, X1.z);
            }
        }
    }

    float* p = g_part + ((long)(b * S1B + blk)) * (DKC * DVC);
#pragma unroll
    for (int jl = 0; jl < 4; jl++) {
        const int j = (jg * 4 + jl) * 8 + 2 * tg;
        *(float2*)(p + (kd0 + g) * DVC + j)     = make_float2(acc[jl][0], acc[jl][1]);
        *(float2*)(p + (kd0 + g + 8) * DVC + j) = make_float2(acc[jl][2], acc[jl][3]);
    }
}

// ============================================================================
// Phase 1b: fold S1B partials -> g_ktv (16MB read, coalesced)
// ============================================================================
__global__ __launch_bounds__(256) void reduce_kernel()
{
    const int o = blockIdx.x * 256 + threadIdx.x;
    const int b = o >> 12;
    const int r = o & 4095;
    const float* p = g_part + (long)b * S1B * 4096 + r;
    float s = 0.f;
#pragma unroll 8
    for (int i = 0; i < S1B; i++) s += p[i * 4096];
    g_ktv[o] = s;
}

// ============================================================================
// Phase 2: out = q^T @ ktv.
// Block 256 thr = 8 warps: warp = (ng 0..3, jg 0..1); warp tile 32n x 32j.
// mma m16n8k16: m=n, k=dk, n'=j.
//   A = q_tile[dk][n] fp32 (split+paired along dk in-loop);
//   B = ktv pre-split packed [dk-rowpair][g][jt][hi,lo].
// 51.2 KB dynamic smem.
// ============================================================================
__global__ __launch_bounds__(256, 3) void phase2_kernel(
    const float* __restrict__ q, float* __restrict__ out)
{
    extern __shared__ uint32_t p2sm[];
    float*    qs = (float*)p2sm;          // [64][QS2]
    uint32_t* kp = p2sm + DKC * QS2;      // [32 rowpairs][KTP]

    const int b    = blockIdx.y;
    const int n0   = blockIdx.x * 128;
    const int t    = threadIdx.x;
    const int w    = t >> 5;
    const int ng   = w >> 1;
    const int jg   = w & 1;
    const int lane = t & 31;
    const int g    = lane >> 2;
    const int tg   = lane & 3;

    // stage ktv: split + pair consecutive dk rows (2 tasks/thread)
    {
        const float4* src = (const float4*)(g_ktv + b * (DKC * DVC));
#pragma unroll
        for (int i = 0; i < 2; i++) {
            int task = t + i * 256;           // 0..511
            int rp = task >> 4, c4 = task & 15;
            float4 r0 = src[(2 * rp) * 16 + c4];
            float4 r1 = src[(2 * rp + 1) * 16 + c4];
            const float* f0 = (const float*)&r0;
            const float* f1 = (const float*)&r1;
#pragma unroll
            for (int e = 0; e < 4; e++) {
                int j = c4 * 4 + e;
                uint32_t hi, lo;
                split_pair(f0[e], f1[e], hi, lo);  // low half = even dk row
                *(uint2*)(kp + rp * KTP + (j & 7) * 16 + (j >> 3) * 2) =
                    make_uint2(hi, lo);
            }
        }
    }
    // stage q tile fp32 (coalesced along n): 8192 elems, 32 per thread
    {
        const float* qb = q + (long)b * DKC * NSEQ + n0;
#pragma unroll 8
        for (int i = 0; i < 32; i++) {
            int idx = t + i * 256;
            int kd = idx >> 7, col = idx & 127;
            qs[kd * QS2 + col] = qb[(long)kd * NSEQ + col];
        }
    }
    __syncthreads();

    float acc[2][4][4];
#pragma unroll
    for (int mt = 0; mt < 2; mt++)
#pragma unroll
        for (int jl = 0; jl < 4; jl++)
#pragma unroll
            for (int p = 0; p < 4; p++) acc[mt][jl][p] = 0.f;

#pragma unroll
    for (int c = 0; c < 4; c++) {                 // four 16-dk chunks
        const int d0 = 16 * c + 2 * tg;
        const int d2 = d0 + 8;

        uint32_t ah[2][4], al[2][4];
#pragma unroll
        for (int mt = 0; mt < 2; mt++) {
            const int ncol = 32 * ng + 16 * mt + g;
            split_pair(qs[d0 * QS2 + ncol],     qs[(d0 + 1) * QS2 + ncol],     ah[mt][0], al[mt][0]);
            split_pair(qs[d0 * QS2 + ncol + 8], qs[(d0 + 1) * QS2 + ncol + 8], ah[mt][1], al[mt][1]);
            split_pair(qs[d2 * QS2 + ncol],     qs[(d2 + 1) * QS2 + ncol],     ah[mt][2], al[mt][2]);
            split_pair(qs[d2 * QS2 + ncol + 8], qs[(d2 + 1) * QS2 + ncol + 8], ah[mt][3], al[mt][3]);
        }

        const uint32_t* p0 = kp + (8 * c + tg) * KTP + g * 16 + jg * 8;
        const uint32_t* p1 = p0 + 4 * KTP;
#pragma unroll
        for (int qv = 0; qv < 2; qv++) {
            uint4 X0 = *(const uint4*)(p0 + qv * 4);
            uint4 X1 = *(const uint4*)(p1 + qv * 4);
            const int j0 = 2 * qv, j1 = j0 + 1;
#pragma unroll
            for (int mt = 0; mt < 2; mt++) {
                mma_bf16(acc[mt][j0], ah[mt], X0.x, X1.x);
                mma_bf16(acc[mt][j0], ah[mt], X0.y, X1.y);
                mma_bf16(acc[mt][j0], al[mt], X0.x, X1.x);
                mma_bf16(acc[mt][j1], ah[mt], X0.z, X1.z);
                mma_bf16(acc[mt][j1], ah[mt], X0.w, X1.w);
                mma_bf16(acc[mt][j1], al[mt], X0.z, X1.z);
            }
        }
    }

#pragma unroll
    for (int mt = 0; mt < 2; mt++) {
        const int nrow = n0 + 32 * ng + 16 * mt + g;
        float* o0 = out + ((long)b * NSEQ + nrow) * DVC;
        float* o1 = out + ((long)b * NSEQ + nrow + 8) * DVC;
#pragma unroll
        for (int jl = 0; jl < 4; jl++) {
            const int j = (jg * 4 + jl) * 8 + 2 * tg;
            *(float2*)(o0 + j) = make_float2(acc[mt][jl][0], acc[mt][jl][1]);
            *(float2*)(o1 + j) = make_float2(acc[mt][jl][2], acc[mt][jl][3]);
        }
    }
}

extern "C" void kernel_launch(void* const* d_in, const int* in_sizes, int n_in,
                              void* d_out, int out_size)
{
    const float* q = (const float*)d_in[0];
    const float* k = (const float*)d_in[1];
    const float* v = (const float*)d_in[2];
    float* out = (float*)d_out;

    cudaFuncSetAttribute(phase2_kernel, cudaFuncAttributeMaxDynamicSharedMemorySize, P2_SMEM);

    phase1_kernel<<<dim3(S1B, BATCH), 256>>>(k, v);
    reduce_kernel<<<(BATCH * DKC * DVC) / 256, 256>>>();
    phase2_kernel<<<dim3(NSEQ / 128, BATCH), 256, P2_SMEM>>>(q, out);
}